// round 3
// baseline (speedup 1.0000x reference)
#include <cuda_runtime.h>
#include <math.h>
#include <stdint.h>

#define N_NODES 50000
#define NPAD    50048   // 391 * 128 ; also 782 * 64
#define FEAT    256
#define E_MAX   1600000

// ---------------- static scratch (no allocation allowed) ----------------
__device__ float g_hA[(size_t)NPAD * FEAT];
__device__ float g_hB[(size_t)NPAD * FEAT];
__device__ float g_agg[(size_t)NPAD * FEAT];
__device__ float g_dis[NPAD];
__device__ int   g_cnt[NPAD];
__device__ int   g_row_ptr[NPAD + 1];
__device__ int   g_cursor[NPAD];
__device__ int   g_csr_src[E_MAX];
__device__ float g_csr_c[E_MAX];
__device__ int   g_bsum[64];

// ---------------- degree / CSR construction ----------------
__global__ void cnt_init_kernel() {
    int i = blockIdx.x * blockDim.x + threadIdx.x;
    if (i < NPAD) g_cnt[i] = 0;
}

__global__ void deg_count_kernel(const int* __restrict__ dst, int E) {
    int e = blockIdx.x * blockDim.x + threadIdx.x;
    if (e < E) atomicAdd(&g_cnt[dst[e]], 1);
}

__global__ void dis_kernel() {
    int i = blockIdx.x * blockDim.x + threadIdx.x;
    if (i < NPAD) g_dis[i] = (i < N_NODES) ? rsqrtf((float)(g_cnt[i] + 1)) : 0.0f;
}

// 3-phase parallel exclusive scan of g_cnt -> g_row_ptr/g_cursor
__global__ void scan1_kernel() {
    __shared__ int sh[1024];
    int tid = threadIdx.x;
    int i = blockIdx.x * 1024 + tid;
    int v = (i < NPAD) ? g_cnt[i] : 0;
    sh[tid] = v;
    __syncthreads();
    for (int off = 1; off < 1024; off <<= 1) {
        int t = (tid >= off) ? sh[tid - off] : 0;
        __syncthreads();
        sh[tid] += t;
        __syncthreads();
    }
    if (i < NPAD) g_row_ptr[i] = sh[tid] - v;  // block-local exclusive
    if (tid == 1023) g_bsum[blockIdx.x] = sh[1023];
}

__global__ void scan2_kernel(int nb) {
    __shared__ int sh[64];
    int tid = threadIdx.x;
    int v = (tid < nb) ? g_bsum[tid] : 0;
    sh[tid] = v;
    __syncthreads();
    for (int off = 1; off < 64; off <<= 1) {
        int t = (tid >= off) ? sh[tid - off] : 0;
        __syncthreads();
        sh[tid] += t;
        __syncthreads();
    }
    g_bsum[tid] = sh[tid] - v;  // exclusive over block sums
}

__global__ void scan3_kernel(int E) {
    int i = blockIdx.x * 1024 + threadIdx.x;
    if (i < NPAD) {
        int r = g_row_ptr[i] + g_bsum[blockIdx.x];
        g_row_ptr[i] = r;
        g_cursor[i] = r;
    }
    if (i == 0) g_row_ptr[NPAD] = E;
}

__global__ void fill_kernel(const int* __restrict__ src, const int* __restrict__ dst, int E) {
    int e = blockIdx.x * blockDim.x + threadIdx.x;
    if (e >= E) return;
    int s = src[e];
    int d = dst[e];
    int pos = atomicAdd(&g_cursor[d], 1);
    g_csr_src[pos] = s;
    g_csr_c[pos] = g_dis[s];
}

// ---------------- CSR gather: agg[d] = dis[d]*(sum dis[s]*h[s] + dis[d]*h[d]) --
template <int F4>
__global__ __launch_bounds__(256) void gather_kernel(const float* __restrict__ h,
                                                     float* __restrict__ agg) {
    const int VPL = F4 / 32;
    int node = blockIdx.x * 8 + (threadIdx.x >> 5);
    if (node >= NPAD) return;
    int lane = threadIdx.x & 31;
    float4* ap = (float4*)agg + (size_t)node * F4 + lane;

    if (node >= N_NODES) {
        float4 z = make_float4(0.f, 0.f, 0.f, 0.f);
#pragma unroll
        for (int v = 0; v < VPL; v++) ap[32 * v] = z;
        return;
    }

    const float4* h4 = (const float4*)h;
    float dd = g_dis[node];

    float4 acc[VPL];
    {
        const float4* hn = h4 + (size_t)node * F4 + lane;
#pragma unroll
        for (int v = 0; v < VPL; v++) {
            float4 t = hn[32 * v];
            acc[v] = make_float4(t.x * dd, t.y * dd, t.z * dd, t.w * dd);
        }
    }

    int beg = g_row_ptr[node];
    int end = g_row_ptr[node + 1];
    int e = beg;
    int n4 = beg + ((end - beg) & ~3);
    for (; e < n4; e += 4) {
        int s0 = g_csr_src[e + 0], s1 = g_csr_src[e + 1];
        int s2 = g_csr_src[e + 2], s3 = g_csr_src[e + 3];
        float c0 = g_csr_c[e + 0], c1 = g_csr_c[e + 1];
        float c2 = g_csr_c[e + 2], c3 = g_csr_c[e + 3];
#pragma unroll
        for (int v = 0; v < VPL; v++) {
            float4 x0 = h4[(size_t)s0 * F4 + lane + 32 * v];
            float4 x1 = h4[(size_t)s1 * F4 + lane + 32 * v];
            float4 x2 = h4[(size_t)s2 * F4 + lane + 32 * v];
            float4 x3 = h4[(size_t)s3 * F4 + lane + 32 * v];
            acc[v].x += c0 * x0.x + c1 * x1.x + c2 * x2.x + c3 * x3.x;
            acc[v].y += c0 * x0.y + c1 * x1.y + c2 * x2.y + c3 * x3.y;
            acc[v].z += c0 * x0.z + c1 * x1.z + c2 * x2.z + c3 * x3.z;
            acc[v].w += c0 * x0.w + c1 * x1.w + c2 * x2.w + c3 * x3.w;
        }
    }
    for (; e < end; e++) {
        int s = g_csr_src[e];
        float c = g_csr_c[e];
#pragma unroll
        for (int v = 0; v < VPL; v++) {
            float4 x = h4[(size_t)s * F4 + lane + 32 * v];
            acc[v].x += c * x.x;
            acc[v].y += c * x.y;
            acc[v].z += c * x.z;
            acc[v].w += c * x.w;
        }
    }

#pragma unroll
    for (int v = 0; v < VPL; v++) {
        ap[32 * v] = make_float4(acc[v].x * dd, acc[v].y * dd, acc[v].z * dd, acc[v].w * dd);
    }
}

// ---------------- TF32 tensor-core GEMM + bias + nan_to_num + LN + skip + relu
__device__ __forceinline__ float n2n(float x) {
    if (isnan(x)) return 0.0f;
    if (isinf(x)) return x > 0.0f ? 1e-5f : -1e-5f;
    return x;
}

__device__ __forceinline__ uint32_t f2tf(float f) {
    uint32_t u;
    asm("cvt.rna.tf32.f32 %0, %1;" : "=r"(u) : "f"(f));
    return u;
}

__device__ __forceinline__ void mma8(float4& c, uint32_t a0, uint32_t a1, uint32_t a2,
                                     uint32_t a3, uint32_t b0, uint32_t b1) {
    asm volatile(
        "mma.sync.aligned.m16n8k8.row.col.f32.tf32.tf32.f32 "
        "{%0,%1,%2,%3},{%4,%5,%6,%7},{%8,%9},{%0,%1,%2,%3};"
        : "+f"(c.x), "+f"(c.y), "+f"(c.z), "+f"(c.w)
        : "r"(a0), "r"(a1), "r"(a2), "r"(a3), "r"(b0), "r"(b1));
}

#define AS_LD 72
#define BS_LD 264

// Block: 256 threads (8 warps). Tile: BM=64, BN=256, BK=32.
// Warps: wm = wid>>2 (2 in M), wn = wid&3 (4 in N). Warp tile 32x64.
__global__ __launch_bounds__(256, 1) void gemm_ln_tf32(const float* __restrict__ A,
                                                       const float* __restrict__ W,
                                                       const float* __restrict__ bias,
                                                       const float* __restrict__ gam,
                                                       const float* __restrict__ bet,
                                                       const float* __restrict__ hskip,
                                                       float* __restrict__ out,
                                                       int K, int do_skip, int do_relu) {
    __shared__ uint32_t As[32][AS_LD];
    __shared__ uint32_t Bs[32][BS_LD];
    __shared__ float ps[64][4];
    __shared__ float pq[64][4];

    const int tid = threadIdx.x;
    const int bx = blockIdx.x;
    const int wid = tid >> 5, lane = tid & 31;
    const int wm = wid >> 2, wn = wid & 3;
    const int g = lane >> 2, t = lane & 3;

    float4 acc[2][8];
#pragma unroll
    for (int mt = 0; mt < 2; mt++)
#pragma unroll
        for (int nt = 0; nt < 8; nt++) acc[mt][nt] = make_float4(0.f, 0.f, 0.f, 0.f);

    const float* Ab = A + (size_t)(bx * 64) * K;

    const int a_row = tid >> 2;            // 0..63
    const int a_k = (tid & 3) * 8;         // 0,8,16,24
    const int b_k = tid >> 3;              // 0..31
    const int b_c = (tid & 7) * 32;        // 0..224

    for (int k0 = 0; k0 < K; k0 += 32) {
        // A: 64x32 -> As[k][m] (tf32)
        {
            const float* p = Ab + (size_t)a_row * K + k0 + a_k;
            float4 v0 = *(const float4*)p;
            float4 v1 = *(const float4*)(p + 4);
            As[a_k + 0][a_row] = f2tf(v0.x);
            As[a_k + 1][a_row] = f2tf(v0.y);
            As[a_k + 2][a_row] = f2tf(v0.z);
            As[a_k + 3][a_row] = f2tf(v0.w);
            As[a_k + 4][a_row] = f2tf(v1.x);
            As[a_k + 5][a_row] = f2tf(v1.y);
            As[a_k + 6][a_row] = f2tf(v1.z);
            As[a_k + 7][a_row] = f2tf(v1.w);
        }
        // B: 32x256 -> Bs[k][n] (tf32)
        {
            const float* p = W + (size_t)(k0 + b_k) * 256 + b_c;
#pragma unroll
            for (int j = 0; j < 8; j++) {
                float4 v = *(const float4*)(p + j * 4);
                uint4 u;
                u.x = f2tf(v.x); u.y = f2tf(v.y); u.z = f2tf(v.z); u.w = f2tf(v.w);
                *(uint4*)&Bs[b_k][b_c + j * 4] = u;
            }
        }
        __syncthreads();
#pragma unroll
        for (int kk = 0; kk < 32; kk += 8) {
            uint32_t af[2][4];
#pragma unroll
            for (int mt = 0; mt < 2; mt++) {
                int m0 = wm * 32 + mt * 16;
                af[mt][0] = As[kk + t][m0 + g];
                af[mt][1] = As[kk + t][m0 + g + 8];
                af[mt][2] = As[kk + t + 4][m0 + g];
                af[mt][3] = As[kk + t + 4][m0 + g + 8];
            }
#pragma unroll
            for (int nt = 0; nt < 8; nt++) {
                int n0 = wn * 64 + nt * 8;
                uint32_t b0 = Bs[kk + t][n0 + g];
                uint32_t b1 = Bs[kk + t + 4][n0 + g];
                mma8(acc[0][nt], af[0][0], af[0][1], af[0][2], af[0][3], b0, b1);
                mma8(acc[1][nt], af[1][0], af[1][1], af[1][2], af[1][3], b0, b1);
            }
        }
        __syncthreads();
    }

    // ---- epilogue: bias + n2n + partial row sums ----
#pragma unroll
    for (int mt = 0; mt < 2; mt++) {
        float rs0 = 0.f, rs1 = 0.f, rq0 = 0.f, rq1 = 0.f;
#pragma unroll
        for (int nt = 0; nt < 8; nt++) {
            float2 bb = *(const float2*)(bias + wn * 64 + nt * 8 + t * 2);
            float4 v = acc[mt][nt];
            v.x = n2n(v.x + bb.x);
            v.y = n2n(v.y + bb.y);
            v.z = n2n(v.z + bb.x);
            v.w = n2n(v.w + bb.y);
            acc[mt][nt] = v;
            rs0 += v.x + v.y; rq0 += v.x * v.x + v.y * v.y;
            rs1 += v.z + v.w; rq1 += v.z * v.z + v.w * v.w;
        }
#pragma unroll
        for (int o = 1; o < 4; o <<= 1) {
            rs0 += __shfl_xor_sync(0xFFFFFFFFu, rs0, o);
            rs1 += __shfl_xor_sync(0xFFFFFFFFu, rs1, o);
            rq0 += __shfl_xor_sync(0xFFFFFFFFu, rq0, o);
            rq1 += __shfl_xor_sync(0xFFFFFFFFu, rq1, o);
        }
        if (t == 0) {
            int r0 = wm * 32 + mt * 16 + g;
            ps[r0][wn] = rs0; pq[r0][wn] = rq0;
            ps[r0 + 8][wn] = rs1; pq[r0 + 8][wn] = rq1;
        }
    }
    __syncthreads();

#pragma unroll
    for (int mt = 0; mt < 2; mt++) {
        int r0 = wm * 32 + mt * 16 + g;
        int r1 = r0 + 8;
        float S0 = ps[r0][0] + ps[r0][1] + ps[r0][2] + ps[r0][3];
        float Q0 = pq[r0][0] + pq[r0][1] + pq[r0][2] + pq[r0][3];
        float S1 = ps[r1][0] + ps[r1][1] + ps[r1][2] + ps[r1][3];
        float Q1 = pq[r1][0] + pq[r1][1] + pq[r1][2] + pq[r1][3];
        float mu0 = S0 * (1.0f / 256.0f);
        float mu1 = S1 * (1.0f / 256.0f);
        float var0 = fmaxf(Q0 * (1.0f / 256.0f) - mu0 * mu0, 0.0f);
        float var1 = fmaxf(Q1 * (1.0f / 256.0f) - mu1 * mu1, 0.0f);
        float ir0 = rsqrtf(var0 + 1e-5f);
        float ir1 = rsqrtf(var1 + 1e-5f);
        int grow0 = bx * 64 + r0;
        int grow1 = bx * 64 + r1;
        bool ok0 = grow0 < N_NODES, ok1 = grow1 < N_NODES;

#pragma unroll
        for (int nt = 0; nt < 8; nt++) {
            int col = wn * 64 + nt * 8 + t * 2;
            float2 gg = *(const float2*)(gam + col);
            float2 ee = *(const float2*)(bet + col);
            float4 v = acc[mt][nt];
            float y0 = (v.x - mu0) * ir0 * gg.x + ee.x;
            float y1 = (v.y - mu0) * ir0 * gg.y + ee.y;
            float y2 = (v.z - mu1) * ir1 * gg.x + ee.x;
            float y3 = (v.w - mu1) * ir1 * gg.y + ee.y;
            if (ok0) {
                if (do_skip) {
                    float2 s = *(const float2*)(hskip + (size_t)grow0 * 256 + col);
                    y0 += s.x; y1 += s.y;
                }
                if (do_relu) { y0 = fmaxf(y0, 0.f); y1 = fmaxf(y1, 0.f); }
                *(float2*)(out + (size_t)grow0 * 256 + col) = make_float2(y0, y1);
            }
            if (ok1) {
                if (do_skip) {
                    float2 s = *(const float2*)(hskip + (size_t)grow1 * 256 + col);
                    y2 += s.x; y3 += s.y;
                }
                if (do_relu) { y2 = fmaxf(y2, 0.f); y3 = fmaxf(y3, 0.f); }
                *(float2*)(out + (size_t)grow1 * 256 + col) = make_float2(y2, y3);
            }
        }
    }
}

// ---------------- host side ---------------------------------------------------
extern "C" void kernel_launch(void* const* d_in, const int* in_sizes, int n_in,
                              void* d_out, int out_size) {
    const float* x = (const float*)d_in[0];
    const int* ei = (const int*)d_in[1];
    const int E = in_sizes[1] / 2;
    const int* src = ei;
    const int* dst = ei + E;

    const float *W[4], *Bv[4], *G[4], *BE[4];
    bool sig_order = (in_sizes[4] > 1024);
    if (!sig_order) {
        for (int i = 0; i < 4; i++) {
            W[i]  = (const float*)d_in[2 + 4 * i];
            Bv[i] = (const float*)d_in[3 + 4 * i];
            G[i]  = (const float*)d_in[4 + 4 * i];
            BE[i] = (const float*)d_in[5 + 4 * i];
        }
    } else {
        for (int i = 0; i < 4; i++) {
            W[i]  = (const float*)d_in[2 + 2 * i];
            Bv[i] = (const float*)d_in[3 + 2 * i];
            G[i]  = (const float*)d_in[10 + 2 * i];
            BE[i] = (const float*)d_in[11 + 2 * i];
        }
    }

    float *hA, *hB, *agg;
    cudaGetSymbolAddress((void**)&hA, g_hA);
    cudaGetSymbolAddress((void**)&hB, g_hB);
    cudaGetSymbolAddress((void**)&agg, g_agg);
    float* out = (float*)d_out;

    // build normalization + CSR
    const int nb = (NPAD + 1023) / 1024;  // 49
    cnt_init_kernel<<<(NPAD + 255) / 256, 256>>>();
    deg_count_kernel<<<(E + 255) / 256, 256>>>(dst, E);
    dis_kernel<<<(NPAD + 255) / 256, 256>>>();
    scan1_kernel<<<nb, 1024>>>();
    scan2_kernel<<<1, 64>>>(nb);
    scan3_kernel<<<nb, 1024>>>(E);
    fill_kernel<<<(E + 255) / 256, 256>>>(src, dst, E);

    const int gather_grid = NPAD / 8;
    const int gemm_grid = NPAD / 64;

    // layer 0: x (128) -> hA, no skip, relu
    gather_kernel<32><<<gather_grid, 256>>>(x, agg);
    gemm_ln_tf32<<<gemm_grid, 256>>>(agg, W[0], Bv[0], G[0], BE[0], nullptr, hA, 128, 0, 1);

    // layer 1: hA -> hB, skip hA, relu
    gather_kernel<64><<<gather_grid, 256>>>(hA, agg);
    gemm_ln_tf32<<<gemm_grid, 256>>>(agg, W[1], Bv[1], G[1], BE[1], hA, hB, 256, 1, 1);

    // layer 2: hB -> hA, skip hB, relu
    gather_kernel<64><<<gather_grid, 256>>>(hB, agg);
    gemm_ln_tf32<<<gemm_grid, 256>>>(agg, W[2], Bv[2], G[2], BE[2], hB, hA, 256, 1, 1);

    // layer 3: hA -> d_out, skip hA, no relu
    gather_kernel<64><<<gather_grid, 256>>>(hA, agg);
    gemm_ln_tf32<<<gemm_grid, 256>>>(agg, W[3], Bv[3], G[3], BE[3], hA, out, 256, 1, 0);
}

// round 5
// speedup vs baseline: 1.2101x; 1.2101x over previous
#include <cuda_runtime.h>
#include <math.h>
#include <stdint.h>

#define N_NODES 50000
#define NPAD    50048   // 391 * 128 ; also 782 * 64
#define FEAT    256
#define E_MAX   1600000

// ---------------- static scratch (no allocation allowed) ----------------
__device__ float g_hA[(size_t)NPAD * FEAT];
__device__ float g_hB[(size_t)NPAD * FEAT];
__device__ float g_agg[(size_t)NPAD * FEAT];
__device__ float g_dis[NPAD];
__device__ int   g_cnt[NPAD];
__device__ int   g_row_ptr[NPAD + 1];
__device__ int   g_cursor[NPAD];
__device__ int   g_csr_src[E_MAX];
__device__ float g_csr_c[E_MAX];
__device__ int   g_bsum[64];

// ---------------- degree / CSR construction ----------------
__global__ void cnt_init_kernel() {
    int i = blockIdx.x * blockDim.x + threadIdx.x;
    if (i < NPAD) g_cnt[i] = 0;
}

__global__ void deg_count_kernel(const int* __restrict__ dst, int E) {
    int e = blockIdx.x * blockDim.x + threadIdx.x;
    if (e < E) atomicAdd(&g_cnt[dst[e]], 1);
}

__global__ void dis_kernel() {
    int i = blockIdx.x * blockDim.x + threadIdx.x;
    if (i < NPAD) g_dis[i] = (i < N_NODES) ? rsqrtf((float)(g_cnt[i] + 1)) : 0.0f;
}

// 3-phase parallel exclusive scan of g_cnt -> g_row_ptr/g_cursor
__global__ void scan1_kernel() {
    __shared__ int sh[1024];
    int tid = threadIdx.x;
    int i = blockIdx.x * 1024 + tid;
    int v = (i < NPAD) ? g_cnt[i] : 0;
    sh[tid] = v;
    __syncthreads();
    for (int off = 1; off < 1024; off <<= 1) {
        int t = (tid >= off) ? sh[tid - off] : 0;
        __syncthreads();
        sh[tid] += t;
        __syncthreads();
    }
    if (i < NPAD) g_row_ptr[i] = sh[tid] - v;
    if (tid == 1023) g_bsum[blockIdx.x] = sh[1023];
}

__global__ void scan2_kernel(int nb) {
    __shared__ int sh[64];
    int tid = threadIdx.x;
    int v = (tid < nb) ? g_bsum[tid] : 0;
    sh[tid] = v;
    __syncthreads();
    for (int off = 1; off < 64; off <<= 1) {
        int t = (tid >= off) ? sh[tid - off] : 0;
        __syncthreads();
        sh[tid] += t;
        __syncthreads();
    }
    g_bsum[tid] = sh[tid] - v;
}

__global__ void scan3_kernel(int E) {
    int i = blockIdx.x * 1024 + threadIdx.x;
    if (i < NPAD) {
        int r = g_row_ptr[i] + g_bsum[blockIdx.x];
        g_row_ptr[i] = r;
        g_cursor[i] = r;
    }
    if (i == 0) g_row_ptr[NPAD] = E;
}

__global__ void fill_kernel(const int* __restrict__ src, const int* __restrict__ dst, int E) {
    int e = blockIdx.x * blockDim.x + threadIdx.x;
    if (e >= E) return;
    int s = src[e];
    int d = dst[e];
    int pos = atomicAdd(&g_cursor[d], 1);
    g_csr_src[pos] = s;
    g_csr_c[pos] = g_dis[s];
}

// ---------------- CSR gather: agg[d] = dis[d]*(sum dis[s]*h[s] + dis[d]*h[d]) --
template <int F4>
__global__ __launch_bounds__(256) void gather_kernel(const float* __restrict__ h,
                                                     float* __restrict__ agg) {
    const int VPL = F4 / 32;
    int node = blockIdx.x * 8 + (threadIdx.x >> 5);
    if (node >= NPAD) return;
    int lane = threadIdx.x & 31;
    float4* ap = (float4*)agg + (size_t)node * F4 + lane;

    if (node >= N_NODES) {
        float4 z = make_float4(0.f, 0.f, 0.f, 0.f);
#pragma unroll
        for (int v = 0; v < VPL; v++) ap[32 * v] = z;
        return;
    }

    const float4* h4 = (const float4*)h;
    float dd = g_dis[node];

    float4 acc[VPL];
    {
        const float4* hn = h4 + (size_t)node * F4 + lane;
#pragma unroll
        for (int v = 0; v < VPL; v++) {
            float4 t = hn[32 * v];
            acc[v] = make_float4(t.x * dd, t.y * dd, t.z * dd, t.w * dd);
        }
    }

    int beg = g_row_ptr[node];
    int end = g_row_ptr[node + 1];
    int e = beg;
    int n4 = beg + ((end - beg) & ~3);
    for (; e < n4; e += 4) {
        int s0 = g_csr_src[e + 0], s1 = g_csr_src[e + 1];
        int s2 = g_csr_src[e + 2], s3 = g_csr_src[e + 3];
        float c0 = g_csr_c[e + 0], c1 = g_csr_c[e + 1];
        float c2 = g_csr_c[e + 2], c3 = g_csr_c[e + 3];
#pragma unroll
        for (int v = 0; v < VPL; v++) {
            float4 x0 = h4[(size_t)s0 * F4 + lane + 32 * v];
            float4 x1 = h4[(size_t)s1 * F4 + lane + 32 * v];
            float4 x2 = h4[(size_t)s2 * F4 + lane + 32 * v];
            float4 x3 = h4[(size_t)s3 * F4 + lane + 32 * v];
            acc[v].x += c0 * x0.x + c1 * x1.x + c2 * x2.x + c3 * x3.x;
            acc[v].y += c0 * x0.y + c1 * x1.y + c2 * x2.y + c3 * x3.y;
            acc[v].z += c0 * x0.z + c1 * x1.z + c2 * x2.z + c3 * x3.z;
            acc[v].w += c0 * x0.w + c1 * x1.w + c2 * x2.w + c3 * x3.w;
        }
    }
    for (; e < end; e++) {
        int s = g_csr_src[e];
        float c = g_csr_c[e];
#pragma unroll
        for (int v = 0; v < VPL; v++) {
            float4 x = h4[(size_t)s * F4 + lane + 32 * v];
            acc[v].x += c * x.x;
            acc[v].y += c * x.y;
            acc[v].z += c * x.z;
            acc[v].w += c * x.w;
        }
    }

#pragma unroll
    for (int v = 0; v < VPL; v++) {
        ap[32 * v] = make_float4(acc[v].x * dd, acc[v].y * dd, acc[v].z * dd, acc[v].w * dd);
    }
}

// ---------------- TF32 tensor-core GEMM + bias + nan_to_num + LN + skip + relu
__device__ __forceinline__ float n2n(float x) {
    if (isnan(x)) return 0.0f;
    if (isinf(x)) return x > 0.0f ? 1e-5f : -1e-5f;
    return x;
}

__device__ __forceinline__ uint32_t f2tf(float f) {
    uint32_t u;
    asm("cvt.rna.tf32.f32 %0, %1;" : "=r"(u) : "f"(f));
    return u;
}

__device__ __forceinline__ void mma8(float4& c, uint32_t a0, uint32_t a1, uint32_t a2,
                                     uint32_t a3, uint32_t b0, uint32_t b1) {
    asm volatile(
        "mma.sync.aligned.m16n8k8.row.col.f32.tf32.tf32.f32 "
        "{%0,%1,%2,%3},{%4,%5,%6,%7},{%8,%9},{%0,%1,%2,%3};"
        : "+f"(c.x), "+f"(c.y), "+f"(c.z), "+f"(c.w)
        : "r"(a0), "r"(a1), "r"(a2), "r"(a3), "r"(b0), "r"(b1));
}

// Block: 256 threads (8 warps). Tile: BM=64, BN=256, BK=32.
// Warps: wm = wid>>2 (2 in M), wn = wid&3 (4 in N). Warp tile 32x64.
// Operands staged in SMEM in mma-fragment layout:
//   A_frag[wmmt][kstep][lane(+pad)][i]  -> inner loop: one uint4 per mt
//   B_frag[kstep][n][t*2+half]          -> inner loop: one uint2 per nt
__global__ __launch_bounds__(256, 2) void gemm_ln_tf32(const float* __restrict__ A,
                                                       const float* __restrict__ W,
                                                       const float* __restrict__ bias,
                                                       const float* __restrict__ gam,
                                                       const float* __restrict__ bet,
                                                       const float* __restrict__ hskip,
                                                       float* __restrict__ out,
                                                       int K, int do_skip, int do_relu) {
    __shared__ __align__(16) uint32_t A_frag[4][4][33][4];   // [m>>4][kstep][lane pad][i]
    __shared__ __align__(16) uint32_t B_frag[4][256][8];     // [kstep][n][t*2+half]
    __shared__ float ps[64][4];
    __shared__ float pq[64][4];

    const int tid = threadIdx.x;
    const int bx = blockIdx.x;
    const int wid = tid >> 5, lane = tid & 31;
    const int wm = wid >> 2, wn = wid & 3;
    const int g = lane >> 2, t = lane & 3;

    float4 acc[2][8];
#pragma unroll
    for (int mt = 0; mt < 2; mt++)
#pragma unroll
        for (int nt = 0; nt < 8; nt++) acc[mt][nt] = make_float4(0.f, 0.f, 0.f, 0.f);

    const float* Ab = A + (size_t)(bx * 64) * K;

    // staging indices
    const int a_row = tid >> 2;            // m: 0..63
    const int a_k = (tid & 3) * 8;         // k base: 0,8,16,24
    const int a_wmmt = a_row >> 4;
    const int a_laneb = (a_row & 7) * 4;
    const int a_im = (a_row >> 3) & 1;
    const int a_kstep = a_k >> 3;

    const int b_k = tid >> 3;              // k: 0..31
    const int b_c = (tid & 7) * 32;        // n base
    const int b_kstep = b_k >> 3;
    const int b_idx = (b_k & 3) * 2 + ((b_k >> 2) & 1);

    for (int k0 = 0; k0 < K; k0 += 32) {
        // stage A (64x32) into fragment layout
        {
            const float* p = Ab + (size_t)a_row * K + k0 + a_k;
            float4 v0 = *(const float4*)p;
            float4 v1 = *(const float4*)(p + 4);
            uint32_t* d0 = &A_frag[a_wmmt][a_kstep][a_laneb][a_im];
            d0[0 * 4]      = f2tf(v0.x);   // j=0: lane+0, i=a_im
            d0[1 * 4]      = f2tf(v0.y);   // j=1
            d0[2 * 4]      = f2tf(v0.z);
            d0[3 * 4]      = f2tf(v0.w);
            d0[0 * 4 + 2]  = f2tf(v1.x);   // j=4..7: half=1 -> i=a_im+2
            d0[1 * 4 + 2]  = f2tf(v1.y);
            d0[2 * 4 + 2]  = f2tf(v1.z);
            d0[3 * 4 + 2]  = f2tf(v1.w);
        }
        // stage B (32x256) into fragment layout
        {
            const float* p = W + (size_t)(k0 + b_k) * 256 + b_c;
            uint32_t* d0 = &B_frag[b_kstep][b_c][b_idx];
#pragma unroll
            for (int jj = 0; jj < 8; jj++) {
                float4 v = *(const float4*)(p + jj * 4);
                d0[(jj * 4 + 0) * 8] = f2tf(v.x);
                d0[(jj * 4 + 1) * 8] = f2tf(v.y);
                d0[(jj * 4 + 2) * 8] = f2tf(v.z);
                d0[(jj * 4 + 3) * 8] = f2tf(v.w);
            }
        }
        __syncthreads();

#pragma unroll
        for (int ks = 0; ks < 4; ks++) {
            uint4 af0 = *(const uint4*)&A_frag[wm * 2 + 0][ks][lane][0];
            uint4 af1 = *(const uint4*)&A_frag[wm * 2 + 1][ks][lane][0];
#pragma unroll
            for (int nt = 0; nt < 8; nt++) {
                uint2 b = *(const uint2*)&B_frag[ks][wn * 64 + nt * 8 + g][t * 2];
                mma8(acc[0][nt], af0.x, af0.y, af0.z, af0.w, b.x, b.y);
                mma8(acc[1][nt], af1.x, af1.y, af1.z, af1.w, b.x, b.y);
            }
        }
        __syncthreads();
    }

    // ---- epilogue: bias + n2n + partial row sums ----
#pragma unroll
    for (int mt = 0; mt < 2; mt++) {
        float rs0 = 0.f, rs1 = 0.f, rq0 = 0.f, rq1 = 0.f;
#pragma unroll
        for (int nt = 0; nt < 8; nt++) {
            float2 bb = *(const float2*)(bias + wn * 64 + nt * 8 + t * 2);
            float4 v = acc[mt][nt];
            v.x = n2n(v.x + bb.x);
            v.y = n2n(v.y + bb.y);
            v.z = n2n(v.z + bb.x);
            v.w = n2n(v.w + bb.y);
            acc[mt][nt] = v;
            rs0 += v.x + v.y; rq0 += v.x * v.x + v.y * v.y;
            rs1 += v.z + v.w; rq1 += v.z * v.z + v.w * v.w;
        }
#pragma unroll
        for (int o = 1; o < 4; o <<= 1) {
            rs0 += __shfl_xor_sync(0xFFFFFFFFu, rs0, o);
            rs1 += __shfl_xor_sync(0xFFFFFFFFu, rs1, o);
            rq0 += __shfl_xor_sync(0xFFFFFFFFu, rq0, o);
            rq1 += __shfl_xor_sync(0xFFFFFFFFu, rq1, o);
        }
        if (t == 0) {
            int r0 = wm * 32 + mt * 16 + g;
            ps[r0][wn] = rs0; pq[r0][wn] = rq0;
            ps[r0 + 8][wn] = rs1; pq[r0 + 8][wn] = rq1;
        }
    }
    __syncthreads();

#pragma unroll
    for (int mt = 0; mt < 2; mt++) {
        int r0 = wm * 32 + mt * 16 + g;
        int r1 = r0 + 8;
        float S0 = ps[r0][0] + ps[r0][1] + ps[r0][2] + ps[r0][3];
        float Q0 = pq[r0][0] + pq[r0][1] + pq[r0][2] + pq[r0][3];
        float S1 = ps[r1][0] + ps[r1][1] + ps[r1][2] + ps[r1][3];
        float Q1 = pq[r1][0] + pq[r1][1] + pq[r1][2] + pq[r1][3];
        float mu0 = S0 * (1.0f / 256.0f);
        float mu1 = S1 * (1.0f / 256.0f);
        float var0 = fmaxf(Q0 * (1.0f / 256.0f) - mu0 * mu0, 0.0f);
        float var1 = fmaxf(Q1 * (1.0f / 256.0f) - mu1 * mu1, 0.0f);
        float ir0 = rsqrtf(var0 + 1e-5f);
        float ir1 = rsqrtf(var1 + 1e-5f);
        int grow0 = bx * 64 + r0;
        int grow1 = bx * 64 + r1;
        bool ok0 = grow0 < N_NODES, ok1 = grow1 < N_NODES;

#pragma unroll
        for (int nt = 0; nt < 8; nt++) {
            int col = wn * 64 + nt * 8 + t * 2;
            float2 gg = *(const float2*)(gam + col);
            float2 ee = *(const float2*)(bet + col);
            float4 v = acc[mt][nt];
            float y0 = (v.x - mu0) * ir0 * gg.x + ee.x;
            float y1 = (v.y - mu0) * ir0 * gg.y + ee.y;
            float y2 = (v.z - mu1) * ir1 * gg.x + ee.x;
            float y3 = (v.w - mu1) * ir1 * gg.y + ee.y;
            if (ok0) {
                if (do_skip) {
                    float2 s = *(const float2*)(hskip + (size_t)grow0 * 256 + col);
                    y0 += s.x; y1 += s.y;
                }
                if (do_relu) { y0 = fmaxf(y0, 0.f); y1 = fmaxf(y1, 0.f); }
                *(float2*)(out + (size_t)grow0 * 256 + col) = make_float2(y0, y1);
            }
            if (ok1) {
                if (do_skip) {
                    float2 s = *(const float2*)(hskip + (size_t)grow1 * 256 + col);
                    y2 += s.x; y3 += s.y;
                }
                if (do_relu) { y2 = fmaxf(y2, 0.f); y3 = fmaxf(y3, 0.f); }
                *(float2*)(out + (size_t)grow1 * 256 + col) = make_float2(y2, y3);
            }
        }
    }
}

// ---------------- host side ---------------------------------------------------
extern "C" void kernel_launch(void* const* d_in, const int* in_sizes, int n_in,
                              void* d_out, int out_size) {
    const float* x = (const float*)d_in[0];
    const int* ei = (const int*)d_in[1];
    const int E = in_sizes[1] / 2;
    const int* src = ei;
    const int* dst = ei + E;

    const float *W[4], *Bv[4], *G[4], *BE[4];
    bool sig_order = (in_sizes[4] > 1024);
    if (!sig_order) {
        for (int i = 0; i < 4; i++) {
            W[i]  = (const float*)d_in[2 + 4 * i];
            Bv[i] = (const float*)d_in[3 + 4 * i];
            G[i]  = (const float*)d_in[4 + 4 * i];
            BE[i] = (const float*)d_in[5 + 4 * i];
        }
    } else {
        for (int i = 0; i < 4; i++) {
            W[i]  = (const float*)d_in[2 + 2 * i];
            Bv[i] = (const float*)d_in[3 + 2 * i];
            G[i]  = (const float*)d_in[10 + 2 * i];
            BE[i] = (const float*)d_in[11 + 2 * i];
        }
    }

    float *hA, *hB, *agg;
    cudaGetSymbolAddress((void**)&hA, g_hA);
    cudaGetSymbolAddress((void**)&hB, g_hB);
    cudaGetSymbolAddress((void**)&agg, g_agg);
    float* out = (float*)d_out;

    // build normalization + CSR
    const int nb = (NPAD + 1023) / 1024;  // 49
    cnt_init_kernel<<<(NPAD + 255) / 256, 256>>>();
    deg_count_kernel<<<(E + 255) / 256, 256>>>(dst, E);
    dis_kernel<<<(NPAD + 255) / 256, 256>>>();
    scan1_kernel<<<nb, 1024>>>();
    scan2_kernel<<<1, 64>>>(nb);
    scan3_kernel<<<nb, 1024>>>(E);
    fill_kernel<<<(E + 255) / 256, 256>>>(src, dst, E);

    const int gather_grid = NPAD / 8;
    const int gemm_grid = NPAD / 64;

    // layer 0: x (128) -> hA, no skip, relu
    gather_kernel<32><<<gather_grid, 256>>>(x, agg);
    gemm_ln_tf32<<<gemm_grid, 256>>>(agg, W[0], Bv[0], G[0], BE[0], nullptr, hA, 128, 0, 1);

    // layer 1: hA -> hB, skip hA, relu
    gather_kernel<64><<<gather_grid, 256>>>(hA, agg);
    gemm_ln_tf32<<<gemm_grid, 256>>>(agg, W[1], Bv[1], G[1], BE[1], hA, hB, 256, 1, 1);

    // layer 2: hB -> hA, skip hB, relu
    gather_kernel<64><<<gather_grid, 256>>>(hB, agg);
    gemm_ln_tf32<<<gemm_grid, 256>>>(agg, W[2], Bv[2], G[2], BE[2], hB, hA, 256, 1, 1);

    // layer 3: hA -> d_out, skip hA, no relu
    gather_kernel<64><<<gather_grid, 256>>>(hA, agg);
    gemm_ln_tf32<<<gemm_grid, 256>>>(agg, W[3], Bv[3], G[3], BE[3], hA, out, 256, 1, 0);
}